// round 2
// baseline (speedup 1.0000x reference)
#include <cuda_runtime.h>

// ---------------- problem constants ----------------
#define NBATCH 32
#define NPTS   1024
#define NCH    256
#define NPROP  256
#define NSAMP  16
#define OUTCH  119

// output layout (flattened concat of reference return tuple, float32)
#define OFF_OBJ     0
#define OFF_CENTER  16384
#define OFF_HS      40960
#define OFF_HRN     139264
#define OFF_HR      237568
#define OFF_SS      335872
#define OFF_SRN     483328
#define OFF_SR      925696
#define OFF_SEM     1368064
#define OFF_NEWXYZ  1515520
#define OFF_INDS    1540096

// ---------------- scratch (device globals; no allocs allowed) ----------------
__device__ int   g_inds[NBATCH * NPROP];
__device__ float g_newxyz[NBATCH * NPROP * 3];
__device__ int   g_idx[NBATCH * NPROP * NSAMP];
__device__ float g_feat[NBATCH * NPROP * 128];

// =====================================================================
// FPS: one block per batch, one thread per point.
// Exact float semantics: (dx*dx + dy*dy) + dz*dz with _rn intrinsics,
// argmax tie-break = first occurrence (max val, then lowest index).
// =====================================================================
__global__ __launch_bounds__(1024) void fps_kernel(const float* __restrict__ xyz) {
    __shared__ float px[NPTS], py[NPTS], pz[NPTS];
    __shared__ float wv[32];
    __shared__ int   wi[32];
    __shared__ float lpt[3];

    const int b   = blockIdx.x;
    const int tid = threadIdx.x;
    const float* xb = xyz + (size_t)b * NPTS * 3;

    float x = xb[tid * 3 + 0];
    float y = xb[tid * 3 + 1];
    float z = xb[tid * 3 + 2];
    px[tid] = x; py[tid] = y; pz[tid] = z;
    float dist = 1e10f;
    __syncthreads();

    if (tid == 0) {
        lpt[0] = px[0]; lpt[1] = py[0]; lpt[2] = pz[0];
        g_inds[b * NPROP] = 0;
        g_newxyz[(b * NPROP) * 3 + 0] = px[0];
        g_newxyz[(b * NPROP) * 3 + 1] = py[0];
        g_newxyz[(b * NPROP) * 3 + 2] = pz[0];
    }
    __syncthreads();

    for (int it = 1; it < NPROP; it++) {
        float dx = x - lpt[0], dy = y - lpt[1], dz = z - lpt[2];
        float d = __fadd_rn(__fadd_rn(__fmul_rn(dx, dx), __fmul_rn(dy, dy)),
                            __fmul_rn(dz, dz));
        dist = fminf(dist, d);

        float v = dist; int id = tid;
        #pragma unroll
        for (int o = 16; o; o >>= 1) {
            float v2 = __shfl_xor_sync(0xffffffffu, v, o);
            int   i2 = __shfl_xor_sync(0xffffffffu, id, o);
            if (v2 > v || (v2 == v && i2 < id)) { v = v2; id = i2; }
        }
        if ((tid & 31) == 0) { wv[tid >> 5] = v; wi[tid >> 5] = id; }
        __syncthreads();
        if (tid < 32) {
            v = wv[tid]; id = wi[tid];
            #pragma unroll
            for (int o = 16; o; o >>= 1) {
                float v2 = __shfl_xor_sync(0xffffffffu, v, o);
                int   i2 = __shfl_xor_sync(0xffffffffu, id, o);
                if (v2 > v || (v2 == v && i2 < id)) { v = v2; id = i2; }
            }
            if (tid == 0) {
                g_inds[b * NPROP + it] = id;
                g_newxyz[(b * NPROP + it) * 3 + 0] = px[id];
                g_newxyz[(b * NPROP + it) * 3 + 1] = py[id];
                g_newxyz[(b * NPROP + it) * 3 + 2] = pz[id];
                lpt[0] = px[id]; lpt[1] = py[id]; lpt[2] = pz[id];
            }
        }
        __syncthreads();
    }
}

// =====================================================================
// Ball query: one warp per (b, p). First NSAMP indices (ascending) with
// d2 < 0.09; pad with the first found (reference semantics).
// =====================================================================
__global__ __launch_bounds__(256) void ball_kernel(const float* __restrict__ xyz) {
    const int gw   = (blockIdx.x * blockDim.x + threadIdx.x) >> 5;
    const int lane = threadIdx.x & 31;
    const int b = gw >> 8;
    const float cx = g_newxyz[gw * 3 + 0];
    const float cy = g_newxyz[gw * 3 + 1];
    const float cz = g_newxyz[gw * 3 + 2];
    const float* xb = xyz + (size_t)b * NPTS * 3;

    int cnt = 0;
    int buf[NSAMP];
    for (int c0 = 0; c0 < NPTS; c0 += 32) {
        const int j = c0 + lane;
        float dx = xb[j * 3 + 0] - cx;
        float dy = xb[j * 3 + 1] - cy;
        float dz = xb[j * 3 + 2] - cz;
        float d = __fadd_rn(__fadd_rn(__fmul_rn(dx, dx), __fmul_rn(dy, dy)),
                            __fmul_rn(dz, dz));
        unsigned m = __ballot_sync(0xffffffffu, d < 0.09f);
        if (lane == 0) {
            while (m && cnt < NSAMP) {
                int t = __ffs(m) - 1;
                buf[cnt++] = c0 + t;
                m &= m - 1;
            }
        }
        cnt = __shfl_sync(0xffffffffu, cnt, 0);
        if (cnt >= NSAMP) break;
    }
    if (lane == 0) {
        const int f = (cnt > 0) ? buf[0] : (NPTS - 1);
        for (int s = cnt; s < NSAMP; s++) buf[s] = f;
        for (int s = 0; s < NSAMP; s++) g_idx[gw * NSAMP + s] = buf[s];
    }
}

// =====================================================================
// Shared-memory GEMM tile: 128 rows x 128 cols, A col-major (ld=132) in
// smem, weights streamed in 16-deep K-chunks. 256 threads, 8x8 micro-tile.
// =====================================================================
__device__ __forceinline__ void gemm_tile(const float* A,
                                          const float* __restrict__ W, int ldw,
                                          int Kdim, int Ncols,
                                          float* wbuf, float acc[8][8],
                                          int tid, int tx, int ty) {
    for (int kt = 0; kt < Kdim; kt += 16) {
        int kc = Kdim - kt; if (kc > 16) kc = 16;
        __syncthreads();
        for (int e = tid; e < (kc << 7); e += 256) {
            const int kk = e >> 7, j = e & 127;
            wbuf[(kk << 7) + j] = (j < Ncols) ? W[(kt + kk) * ldw + j] : 0.f;
        }
        __syncthreads();
        #pragma unroll 4
        for (int kk = 0; kk < kc; kk++) {
            const float4* ap = (const float4*)(A + (kt + kk) * 132 + (ty << 3));
            float4 a0 = ap[0], a1 = ap[1];
            const float4* bp = (const float4*)(wbuf + (kk << 7) + (tx << 3));
            float4 b0 = bp[0], b1 = bp[1];
            float av[8] = {a0.x, a0.y, a0.z, a0.w, a1.x, a1.y, a1.z, a1.w};
            float bv[8] = {b0.x, b0.y, b0.z, b0.w, b1.x, b1.y, b1.z, b1.w};
            #pragma unroll
            for (int i = 0; i < 8; i++)
                #pragma unroll
                for (int j = 0; j < 8; j++)
                    acc[i][j] = fmaf(av[i], bv[j], acc[i][j]);
        }
    }
    __syncthreads();
}

#define ZERO_ACC(acc)                         \
    _Pragma("unroll")                         \
    for (int _i = 0; _i < 8; _i++)            \
        _Pragma("unroll")                     \
        for (int _j = 0; _j < 8; _j++)        \
            acc[_i][_j] = 0.f;

// =====================================================================
// Fused grouping + 3-layer MLP + max-pool over NSAMP.
// Block = (batch b, tile of 8 proposals) -> 128 rows (8 p x 16 s).
// =====================================================================
#define MLP_SMEM ((259 * 132 + 128 * 132 + 16 * 128 + 128) * 4)

__global__ __launch_bounds__(256, 1) void mlp_kernel(
    const float* __restrict__ xyz, const float* __restrict__ feats,
    const float* __restrict__ w0, const float* __restrict__ b0,
    const float* __restrict__ gg0, const float* __restrict__ be0,
    const float* __restrict__ w1, const float* __restrict__ b1,
    const float* __restrict__ gg1, const float* __restrict__ be1,
    const float* __restrict__ w2, const float* __restrict__ b2,
    const float* __restrict__ gg2, const float* __restrict__ be2) {
    extern __shared__ float sm[];
    float* x0   = sm;                       // 259 x 132 (col-major input)
    float* x1   = sm + 259 * 132;           // 128 x 132
    float* wbuf = x1 + 128 * 132;           // 16 x 128
    int*   jrow = (int*)(wbuf + 16 * 128);  // 128

    const int tid = threadIdx.x;
    const int tx = tid & 15, ty = tid >> 4;
    const int b  = blockIdx.x >> 5;
    const int pt = (blockIdx.x & 31) << 3;

    // ---- fill gxyz channels + gather indices ----
    for (int r = tid; r < 128; r += 256) {
        const int p = pt + (r >> 4), s = r & 15;
        const int j = g_idx[((b << 8) + p) * NSAMP + s];
        jrow[r] = j;
        const float* np = g_newxyz + ((b << 8) + p) * 3;
        const float* xp = xyz + ((size_t)b * NPTS + j) * 3;
        x0[0 * 132 + r] = __fdiv_rn(xp[0] - np[0], 0.3f);
        x0[1 * 132 + r] = __fdiv_rn(xp[1] - np[1], 0.3f);
        x0[2 * 132 + r] = __fdiv_rn(xp[2] - np[2], 0.3f);
    }
    __syncthreads();
    // ---- gather features (coalesced over channels) ----
    const float* fb = feats + (size_t)b * NPTS * NCH;
    for (int e = tid; e < 128 * NCH; e += 256) {
        const int r = e >> 8, c = e & 255;
        x0[(3 + c) * 132 + r] = fb[(size_t)jrow[r] * NCH + c];
    }

    float acc[8][8];
    const int j0 = tx << 3, r0 = ty << 3;

    // ---- layer 1: 259 -> 128 ----
    ZERO_ACC(acc);
    gemm_tile(x0, w0, 128, 259, 128, wbuf, acc, tid, tx, ty);
    {
        float gv[8], bvv[8], bev[8];
        #pragma unroll
        for (int jj = 0; jj < 8; jj++) {
            gv[jj] = gg0[j0 + jj]; bvv[jj] = b0[j0 + jj]; bev[jj] = be0[j0 + jj];
        }
        #pragma unroll
        for (int jj = 0; jj < 8; jj++) {
            float t[8];
            #pragma unroll
            for (int i = 0; i < 8; i++)
                t[i] = fmaxf(gv[jj] * (acc[i][jj] + bvv[jj]) + bev[jj], 0.f);
            float* d = x1 + (j0 + jj) * 132 + r0;
            *(float4*)d       = make_float4(t[0], t[1], t[2], t[3]);
            *(float4*)(d + 4) = make_float4(t[4], t[5], t[6], t[7]);
        }
    }

    // ---- layer 2: 128 -> 128 ----
    ZERO_ACC(acc);
    gemm_tile(x1, w1, 128, 128, 128, wbuf, acc, tid, tx, ty);
    {
        float gv[8], bvv[8], bev[8];
        #pragma unroll
        for (int jj = 0; jj < 8; jj++) {
            gv[jj] = gg1[j0 + jj]; bvv[jj] = b1[j0 + jj]; bev[jj] = be1[j0 + jj];
        }
        #pragma unroll
        for (int jj = 0; jj < 8; jj++) {
            float t[8];
            #pragma unroll
            for (int i = 0; i < 8; i++)
                t[i] = fmaxf(gv[jj] * (acc[i][jj] + bvv[jj]) + bev[jj], 0.f);
            float* d = x0 + (j0 + jj) * 132 + r0;
            *(float4*)d       = make_float4(t[0], t[1], t[2], t[3]);
            *(float4*)(d + 4) = make_float4(t[4], t[5], t[6], t[7]);
        }
    }

    // ---- layer 3: 128 -> 128, fused max-pool over 16 samples ----
    ZERO_ACC(acc);
    gemm_tile(x0, w2, 128, 128, 128, wbuf, acc, tid, tx, ty);
    {
        float gv[8], bvv[8], bev[8];
        #pragma unroll
        for (int jj = 0; jj < 8; jj++) {
            gv[jj] = gg2[j0 + jj]; bvv[jj] = b2[j0 + jj]; bev[jj] = be2[j0 + jj];
        }
        float mx[8];
        #pragma unroll
        for (int jj = 0; jj < 8; jj++) {
            float m = -1.f;
            #pragma unroll
            for (int i = 0; i < 8; i++) {
                float u = fmaxf(gv[jj] * (acc[i][jj] + bvv[jj]) + bev[jj], 0.f);
                m = fmaxf(m, u);
            }
            m = fmaxf(m, __shfl_xor_sync(0xffffffffu, m, 16));
            mx[jj] = m;
        }
        if ((ty & 1) == 0) {
            const int p = pt + (ty >> 1);
            float* d = g_feat + (((size_t)(b << 8) + p) << 7) + j0;
            *(float4*)d       = make_float4(mx[0], mx[1], mx[2], mx[3]);
            *(float4*)(d + 4) = make_float4(mx[4], mx[5], mx[6], mx[7]);
        }
    }
}

// =====================================================================
// Head: 2x (FC 128->128, relu6 BN) + FC 128->119 + split/scale/scatter.
// Block = 128 proposal rows. 64 blocks.
// =====================================================================
#define HEAD_SMEM ((128 * 132 * 2 + 16 * 128 + 56) * 4)

__global__ __launch_bounds__(256, 1) void head_kernel(
    const float* __restrict__ w1, const float* __restrict__ b1,
    const float* __restrict__ gg1, const float* __restrict__ be1,
    const float* __restrict__ w2, const float* __restrict__ b2,
    const float* __restrict__ gg2, const float* __restrict__ be2,
    const float* __restrict__ w3, const float* __restrict__ b3,
    const float* __restrict__ msz, float* __restrict__ out) {
    extern __shared__ float sm[];
    float* a0   = sm;              // 128 x 132
    float* a1   = sm + 128 * 132;  // 128 x 132
    float* wbuf = a1 + 128 * 132;  // 16 x 128
    float* ms   = wbuf + 16 * 128; // 54

    const int tid = threadIdx.x;
    const int tx = tid & 15, ty = tid >> 4;
    const int gp0 = blockIdx.x << 7;

    if (tid < 54) ms[tid] = msz[tid];
    for (int e = tid; e < 16384; e += 256) {
        const int r = e >> 7, c = e & 127;
        a0[c * 132 + r] = g_feat[((size_t)(gp0 + r) << 7) + c];
    }

    float acc[8][8];
    const int j0 = tx << 3, r0 = ty << 3;

    // FC1 + relu6 BN
    ZERO_ACC(acc);
    gemm_tile(a0, w1, 128, 128, 128, wbuf, acc, tid, tx, ty);
    {
        float gv[8], bvv[8], bev[8];
        #pragma unroll
        for (int jj = 0; jj < 8; jj++) {
            gv[jj] = gg1[j0 + jj]; bvv[jj] = b1[j0 + jj]; bev[jj] = be1[j0 + jj];
        }
        #pragma unroll
        for (int jj = 0; jj < 8; jj++) {
            float t[8];
            #pragma unroll
            for (int i = 0; i < 8; i++)
                t[i] = fminf(fmaxf(gv[jj] * (acc[i][jj] + bvv[jj]) + bev[jj], 0.f), 6.f);
            float* d = a1 + (j0 + jj) * 132 + r0;
            *(float4*)d       = make_float4(t[0], t[1], t[2], t[3]);
            *(float4*)(d + 4) = make_float4(t[4], t[5], t[6], t[7]);
        }
    }

    // FC2 + relu6 BN
    ZERO_ACC(acc);
    gemm_tile(a1, w2, 128, 128, 128, wbuf, acc, tid, tx, ty);
    {
        float gv[8], bvv[8], bev[8];
        #pragma unroll
        for (int jj = 0; jj < 8; jj++) {
            gv[jj] = gg2[j0 + jj]; bvv[jj] = b2[j0 + jj]; bev[jj] = be2[j0 + jj];
        }
        #pragma unroll
        for (int jj = 0; jj < 8; jj++) {
            float t[8];
            #pragma unroll
            for (int i = 0; i < 8; i++)
                t[i] = fminf(fmaxf(gv[jj] * (acc[i][jj] + bvv[jj]) + bev[jj], 0.f), 6.f);
            float* d = a0 + (j0 + jj) * 132 + r0;
            *(float4*)d       = make_float4(t[0], t[1], t[2], t[3]);
            *(float4*)(d + 4) = make_float4(t[4], t[5], t[6], t[7]);
        }
    }

    // FC3 (119 cols) + scatter epilogue
    ZERO_ACC(acc);
    gemm_tile(a0, w3, OUTCH, 128, OUTCH, wbuf, acc, tid, tx, ty);
    {
        float b3v[8];
        #pragma unroll
        for (int jj = 0; jj < 8; jj++)
            b3v[jj] = (j0 + jj < OUTCH) ? b3[j0 + jj] : 0.f;
        #pragma unroll
        for (int i = 0; i < 8; i++) {
            const int gp = gp0 + r0 + i;
            #pragma unroll
            for (int jj = 0; jj < 8; jj++) {
                const int j = j0 + jj;
                if (j >= OUTCH) continue;
                const float v = acc[i][jj] + b3v[jj];
                if (j < 3) {
                    out[OFF_CENTER + gp * 3 + j] = g_newxyz[gp * 3 + j] + v;
                } else {
                    const int jr = j - 3;
                    if (jr < 2) {
                        out[OFF_OBJ + gp * 2 + jr] = v;
                    } else if (jr < 14) {
                        out[OFF_HS + gp * 12 + (jr - 2)] = v;
                    } else if (jr < 32) {
                        out[OFF_SS + gp * 18 + (jr - 14)] = v;
                    } else if (jr < 44) {
                        const int h = jr - 32;
                        out[OFF_HRN + gp * 12 + h] = v;
                        out[OFF_HR + gp * 12 + h]  = v * 0.26179938779916667f; // PI/NH
                    } else if (jr < 98) {
                        const int t = jr - 44;
                        out[OFF_SRN + gp * 54 + t] = v;
                        out[OFF_SR + gp * 54 + t]  = v * ms[t];
                    } else {
                        out[OFF_SEM + gp * 18 + (jr - 98)] = v;
                    }
                }
            }
        }
    }
}

// =====================================================================
// Tail: write new_xyz and inds (as float) into the output buffer.
// =====================================================================
__global__ __launch_bounds__(256) void tail_kernel(float* __restrict__ out) {
    const int i = blockIdx.x * blockDim.x + threadIdx.x;
    if (i < NBATCH * NPROP * 3) {
        out[OFF_NEWXYZ + i] = g_newxyz[i];
    } else if (i < NBATCH * NPROP * 3 + NBATCH * NPROP) {
        const int k = i - NBATCH * NPROP * 3;
        out[OFF_INDS + k] = (float)g_inds[k];
    }
}

// =====================================================================
extern "C" void kernel_launch(void* const* d_in, const int* in_sizes, int n_in,
                              void* d_out, int out_size) {
    const float* xyz   = (const float*)d_in[0];
    const float* feats = (const float*)d_in[1];
    const float* msz   = (const float*)d_in[2];
    const float* w_m0  = (const float*)d_in[3];
    const float* b_m0  = (const float*)d_in[4];
    const float* g_m0  = (const float*)d_in[5];
    const float* be_m0 = (const float*)d_in[6];
    const float* w_m1  = (const float*)d_in[7];
    const float* b_m1  = (const float*)d_in[8];
    const float* g_m1  = (const float*)d_in[9];
    const float* be_m1 = (const float*)d_in[10];
    const float* w_m2  = (const float*)d_in[11];
    const float* b_m2  = (const float*)d_in[12];
    const float* g_m2  = (const float*)d_in[13];
    const float* be_m2 = (const float*)d_in[14];
    const float* w1    = (const float*)d_in[15];
    const float* b1    = (const float*)d_in[16];
    const float* g1    = (const float*)d_in[17];
    const float* be1   = (const float*)d_in[18];
    const float* w2    = (const float*)d_in[19];
    const float* b2    = (const float*)d_in[20];
    const float* g2    = (const float*)d_in[21];
    const float* be2   = (const float*)d_in[22];
    const float* w3    = (const float*)d_in[23];
    const float* b3    = (const float*)d_in[24];
    float* out = (float*)d_out;

    cudaFuncSetAttribute(mlp_kernel, cudaFuncAttributeMaxDynamicSharedMemorySize, MLP_SMEM);
    cudaFuncSetAttribute(head_kernel, cudaFuncAttributeMaxDynamicSharedMemorySize, HEAD_SMEM);

    fps_kernel<<<NBATCH, 1024>>>(xyz);
    ball_kernel<<<(NBATCH * NPROP * 32) / 256, 256>>>(xyz);
    mlp_kernel<<<NBATCH * (NPROP / 8), 256, MLP_SMEM>>>(
        xyz, feats, w_m0, b_m0, g_m0, be_m0, w_m1, b_m1, g_m1, be_m1,
        w_m2, b_m2, g_m2, be_m2);
    head_kernel<<<(NBATCH * NPROP) / 128, 256, HEAD_SMEM>>>(
        w1, b1, g1, be1, w2, b2, g2, be2, w3, b3, msz, out);
    tail_kernel<<<(NBATCH * NPROP * 4 + 255) / 256, 256>>>(out);
}